// round 10
// baseline (speedup 1.0000x reference)
#include <cuda_runtime.h>
#include <cstdint>

// out[b, i, c] = sum_{j=0..3} x[b, i+j, c] * att[b, i+j]
// x:   [8, 1, 4099, 512] fp32 (evict_last-pinned loads)
// att: [8, 4099] fp32
// out: [8, 1, 4096, 512] fp32 (evict_first streaming stores)
//
// 32-row strips, processed as 2 chunks of 16 with the sliding window carried
// across the chunk boundary: halo read amplification 35/32 (vs 19/16),
// ~6% fewer bytes through the LTS fabric, which is the measured wall.

#define SENT_LEN  4096
#define FW        4
#define ROWS_IN   (SENT_LEN + FW - 1)   // 4099
#define CH        512
#define C4        (CH / 4)              // 128 float4 lanes per row
#define RPB       32                    // output rows per block
#define CHUNK     16                    // rows per inner pass (proven MLP depth)

__device__ __forceinline__ uint64_t make_evict_last_policy() {
    uint64_t pol;
    asm volatile("createpolicy.fractional.L2::evict_last.b64 %0, 1.0;" : "=l"(pol));
    return pol;
}

__device__ __forceinline__ float4 ld_x(const float4* p, uint64_t pol) {
    float4 v;
    asm volatile("ld.global.nc.L2::cache_hint.v4.f32 {%0,%1,%2,%3}, [%4], %5;"
                 : "=f"(v.x), "=f"(v.y), "=f"(v.z), "=f"(v.w)
                 : "l"(p), "l"(pol));
    return v;
}

__device__ __forceinline__ float ld_a(const float* p, uint64_t pol) {
    float v;
    asm volatile("ld.global.nc.L2::cache_hint.f32 %0, [%1], %2;"
                 : "=f"(v) : "l"(p), "l"(pol));
    return v;
}

__global__ __launch_bounds__(C4)
void wp_slide_kernel(const float4* __restrict__ x,
                     const float*  __restrict__ att,
                     float4* __restrict__ out)
{
    const int c4    = threadIdx.x;           // 0..127 (column, coalesced)
    const int strip = blockIdx.x;            // 0..127
    const int b     = blockIdx.y;            // 0..7
    const int i0    = strip * RPB;

    const uint64_t pol = make_evict_last_policy();

    const float4* xp = x   + ((long)b * ROWS_IN + i0) * C4 + c4;
    float4*       op = out + ((long)b * SENT_LEN + i0) * C4 + c4;
    const float*  ap = att + b * ROWS_IN + i0;

    // Preload the first 3 weighted rows of the window
    float a0 = ld_a(ap + 0, pol), a1 = ld_a(ap + 1, pol), a2 = ld_a(ap + 2, pol);
    float4 v;

    v = ld_x(xp + 0 * C4, pol);
    float4 w0 = make_float4(v.x * a0, v.y * a0, v.z * a0, v.w * a0);
    v = ld_x(xp + 1 * C4, pol);
    float4 w1 = make_float4(v.x * a1, v.y * a1, v.z * a1, v.w * a1);
    v = ld_x(xp + 2 * C4, pol);
    float4 w2 = make_float4(v.x * a2, v.y * a2, v.z * a2, v.w * a2);

    #pragma unroll
    for (int cc = 0; cc < RPB / CHUNK; ++cc) {
        const int base = cc * CHUNK;

        // Front-batch the 16 loads of this chunk (proven MLP pattern).
        float4 t[CHUNK];
        float  av[CHUNK];
        #pragma unroll
        for (int r = 0; r < CHUNK; ++r) {
            t[r]  = ld_x(xp + (base + r + 3) * C4, pol);
            av[r] = ld_a(ap + base + r + 3, pol);
        }

        #pragma unroll
        for (int r = 0; r < CHUNK; ++r) {
            const float a3 = av[r];
            const float w3x = t[r].x * a3, w3y = t[r].y * a3,
                        w3z = t[r].z * a3, w3w = t[r].w * a3;
            float4 o;
            o.x = (w0.x + w1.x) + (w2.x + w3x);
            o.y = (w0.y + w1.y) + (w2.y + w3y);
            o.z = (w0.z + w1.z) + (w2.z + w3z);
            o.w = (w0.w + w1.w) + (w2.w + w3w);
            asm volatile("st.global.cs.v4.f32 [%0], {%1,%2,%3,%4};"
                         :: "l"(op + (base + r) * C4),
                            "f"(o.x), "f"(o.y), "f"(o.z), "f"(o.w)
                         : "memory");
            w0 = w1; w1 = w2;
            w2 = make_float4(w3x, w3y, w3z, w3w);
        }
    }
}

extern "C" void kernel_launch(void* const* d_in, const int* in_sizes, int n_in,
                              void* d_out, int out_size)
{
    const float4* x   = (const float4*)d_in[0];
    const float*  att = (const float*)d_in[1];
    float4*       out = (float4*)d_out;

    dim3 grid(SENT_LEN / RPB, 8);   // (128, 8) = 1024 blocks
    dim3 block(C4);                 // 128 threads
    wp_slide_kernel<<<grid, block>>>(x, att, out);
}

// round 11
// speedup vs baseline: 1.0213x; 1.0213x over previous
#include <cuda_runtime.h>
#include <cstdint>

// out[b, i, c] = sum_{j=0..3} x[b, i+j, c] * att[b, i+j]
// x:   [8, 1, 4099, 512] fp32 (evict_last-pinned loads; partial L2 residency
//                              across graph replays is the steady-state win)
// att: [8, 4099] fp32
// out: [8, 1, 4096, 512] fp32 (evict_first streaming stores)
//
// Champion geometry (R7): 16-row strips, 2048 blocks, 128 threads.
// Change vs R7: ALL 19 x-row loads front-batched before any compute/store.

#define SENT_LEN     4096
#define FW           4
#define ROWS_IN      (SENT_LEN + FW - 1)   // 4099
#define CH           512
#define C4           (CH / 4)              // 128 float4 lanes per row
#define ROWS_PER_BLK 16
#define TROWS        (ROWS_PER_BLK + FW - 1)  // 19

__device__ __forceinline__ uint64_t make_evict_last_policy() {
    uint64_t pol;
    asm volatile("createpolicy.fractional.L2::evict_last.b64 %0, 1.0;" : "=l"(pol));
    return pol;
}

__device__ __forceinline__ float4 ld_x(const float4* p, uint64_t pol) {
    float4 v;
    asm volatile("ld.global.nc.L2::cache_hint.v4.f32 {%0,%1,%2,%3}, [%4], %5;"
                 : "=f"(v.x), "=f"(v.y), "=f"(v.z), "=f"(v.w)
                 : "l"(p), "l"(pol));
    return v;
}

__device__ __forceinline__ float ld_a(const float* p, uint64_t pol) {
    float v;
    asm volatile("ld.global.nc.L2::cache_hint.f32 %0, [%1], %2;"
                 : "=f"(v) : "l"(p), "l"(pol));
    return v;
}

__global__ __launch_bounds__(C4, 6)
void wp_slide_kernel(const float4* __restrict__ x,
                     const float*  __restrict__ att,
                     float4* __restrict__ out)
{
    const int c4    = threadIdx.x;           // 0..127 (column, coalesced)
    const int chunk = blockIdx.x;            // 0..255 (row chunk)
    const int b     = blockIdx.y;            // 0..7
    const int i0    = chunk * ROWS_PER_BLK;

    const uint64_t pol = make_evict_last_policy();

    const float4* xp = x   + ((long)b * ROWS_IN + i0) * C4 + c4;
    float4*       op = out + ((long)b * SENT_LEN + i0) * C4 + c4;
    const float*  ap = att + b * ROWS_IN + i0;

    // Front-batch EVERYTHING: 19 x-row loads + 19 att scalars issued
    // back-to-back before any dependent compute.
    float4 t[TROWS];
    float  a[TROWS];
    #pragma unroll
    for (int r = 0; r < TROWS; ++r) t[r] = ld_x(xp + r * C4, pol);
    #pragma unroll
    for (int r = 0; r < TROWS; ++r) a[r] = ld_a(ap + r, pol);

    // Weighted rows for the initial window
    float4 w0 = make_float4(t[0].x * a[0], t[0].y * a[0], t[0].z * a[0], t[0].w * a[0]);
    float4 w1 = make_float4(t[1].x * a[1], t[1].y * a[1], t[1].z * a[1], t[1].w * a[1]);
    float4 w2 = make_float4(t[2].x * a[2], t[2].y * a[2], t[2].z * a[2], t[2].w * a[2]);

    #pragma unroll
    for (int r = 0; r < ROWS_PER_BLK; ++r) {
        const float a3 = a[r + 3];
        const float w3x = t[r + 3].x * a3, w3y = t[r + 3].y * a3,
                    w3z = t[r + 3].z * a3, w3w = t[r + 3].w * a3;
        float4 o;
        o.x = (w0.x + w1.x) + (w2.x + w3x);
        o.y = (w0.y + w1.y) + (w2.y + w3y);
        o.z = (w0.z + w1.z) + (w2.z + w3z);
        o.w = (w0.w + w1.w) + (w2.w + w3w);
        asm volatile("st.global.cs.v4.f32 [%0], {%1,%2,%3,%4};"
                     :: "l"(op + r * C4), "f"(o.x), "f"(o.y), "f"(o.z), "f"(o.w)
                     : "memory");
        w0 = w1; w1 = w2;
        w2 = make_float4(w3x, w3y, w3z, w3w);
    }
}

extern "C" void kernel_launch(void* const* d_in, const int* in_sizes, int n_in,
                              void* d_out, int out_size)
{
    const float4* x   = (const float4*)d_in[0];
    const float*  att = (const float*)d_in[1];
    float4*       out = (float4*)d_out;

    dim3 grid(SENT_LEN / ROWS_PER_BLK, 8);   // (256, 8) = 2048 blocks
    dim3 block(C4);                          // 128 threads
    wp_slide_kernel<<<grid, block>>>(x, att, out);
}